// round 17
// baseline (speedup 1.0000x reference)
#include <cuda_runtime.h>
#include <cuda_fp16.h>
#include <cstdint>

// ============================================================================
// LSTM seq2seq (B=32, T_IN=128, T_OUT=64, H=2048, IO=1) via mma.sync fp16.
//
// R16 resubmit (infra failed; kernel never ran): persistent kernel;
// tree-arrive global barrier (8x16 + root); single-shot 32KB per-quarter
// h fetch (1 cp.async wait/step); x preloaded transposed in SMEM.
// ============================================================================

#define HID 2048
#define TIN 128
#define TOUT 64
#define NSTEP 192
#define NCTA 128
#define AG_HALF 32768          // per (cta,gate): 128 kb16 x 32 lanes x 8 half

// SMEM float offsets (B region = bytes [0, 131072) = 32768 floats)
#define EXPB_F 32768           // partials kq=1..3: 3 x 2112
#define EX_F 39104             // final gates 4 x 528
#define SHH_F 41216            // 16 x 33
#define SFC_F 41744            // 16
#define SRED_F 41760           // 16 x 32
#define XT_F 42272             // x transposed: 128 x 32
#define SX_F 46368             // 32 (decoder computed input)
#define SMEM_BYTES 185600

// ---------------- device scratch --------------------------------------------
__device__ __align__(16) __half g_Aenc[(size_t)NCTA * 4 * AG_HALF];  // 32 MB
__device__ __align__(16) __half g_Adec[(size_t)NCTA * 4 * AG_HALF];  // 32 MB
__device__ __align__(16) __half g_hstage[2][65536];
__device__ __align__(16) float g_c[HID * 32];
__device__ __align__(16) float g_ypart[TOUT * NCTA * 32];
__device__ int g_arr1[8 * 32];   // first-level counters, 128B apart
__device__ int g_arr2 = 0;
__device__ int g_release = 0;

// ---------------- index maps (m16n8k16 f16 fragments) ------------------------
__device__ __forceinline__ int frag_d_row(int lane, int r) { return (lane >> 2) + 8 * (r >> 1); }
__device__ __forceinline__ int frag_d_col(int lane, int r) { return 2 * (lane & 3) + (r & 1); }
// staged-h fragment-major index (halves) for h[k][n], k=unit, n=batch
__device__ __forceinline__ int hidx16(int k, int n) {
    int lane = ((n & 7) << 2) | ((k >> 1) & 3);
    return (k >> 4) * 512 + (n >> 3) * 128 + lane * 4 + ((k >> 3) & 1) * 2 + (k & 1);
}

// ---------------- helpers ----------------------------------------------------
__device__ __forceinline__ void mma_f16(float* d, const uint32_t* a, const uint32_t* b) {
    asm volatile(
        "mma.sync.aligned.m16n8k16.row.col.f32.f16.f16.f32 "
        "{%0,%1,%2,%3}, {%4,%5,%6,%7}, {%8,%9}, {%0,%1,%2,%3};"
        : "+f"(d[0]), "+f"(d[1]), "+f"(d[2]), "+f"(d[3])
        : "r"(a[0]), "r"(a[1]), "r"(a[2]), "r"(a[3]), "r"(b[0]), "r"(b[1]));
}
__device__ __forceinline__ void cp_async16(uint32_t saddr, const void* gaddr) {
    asm volatile("cp.async.cg.shared.global [%0], [%1], 16;" :: "r"(saddr), "l"(gaddr) : "memory");
}
__device__ __forceinline__ uint32_t smem_u32(const void* p) {
    uint32_t a;
    asm("{ .reg .u64 t; cvta.to.shared.u64 t, %1; cvt.u32.u64 %0, t; }" : "=r"(a) : "l"(p));
    return a;
}
__device__ __forceinline__ float ldcg_f(const float* p) {
    float v;
    asm volatile("ld.global.cg.f32 %0, [%1];" : "=f"(v) : "l"(p));
    return v;
}

// ---------------- prep: permute W_hh into fp16 fragment-major layout --------
__global__ void prep_kernel(const float* __restrict__ W, int which) {
    __half* dst = which ? g_Adec : g_Aenc;
    size_t f = (size_t)blockIdx.x * 256 + threadIdx.x;
    int cta = (int)(f >> 17);
    int rem = (int)(f & 0x1FFFF);
    int g = rem >> 15;            // gate
    int rem2 = rem & 0x7FFF;
    int kb = rem2 >> 8;           // kb16 0..127
    int li = rem2 & 255;
    int lane = li >> 3;
    int e = li & 7;
    int j = e >> 1;
    int r = (lane >> 2) + 8 * (j & 1);
    int k = 2 * (lane & 3) + 8 * (j >> 1) + (e & 1);
    int grow = g * HID + cta * 16 + r;
    int gcol = kb * 16 + k;
    dst[f] = __float2half_rn(W[(size_t)grow * HID + gcol]);
}

__global__ void init_kernel() {
    int i = blockIdx.x * blockDim.x + threadIdx.x;
    int n = gridDim.x * blockDim.x;
    for (int j = i; j < 65536; j += n) ((uint32_t*)g_hstage)[j] = 0u;
    for (int j = i; j < HID * 32; j += n) g_c[j] = 0.f;
    if (i < 8 * 32) g_arr1[i] = 0;
    if (i == 0) { g_arr2 = 0; g_release = 0; }
}

__global__ void final_kernel(float* __restrict__ out, const float* __restrict__ fcb) {
    int i = blockIdx.x * blockDim.x + threadIdx.x;
    if (i < 32 * TOUT) {
        int b = i / TOUT, t = i % TOUT;
        float y = fcb[0];
        #pragma unroll 8
        for (int j = 0; j < NCTA; j++) y += g_ypart[(t * NCTA + j) * 32 + b];
        out[i] = y;
    }
}

// ---------------- persistent step kernel ------------------------------------
__global__ void __launch_bounds__(512) step_kernel(
    const float* __restrict__ x,
    const float* __restrict__ Wih_e, const float* __restrict__ b_e,
    const float* __restrict__ Wih_d, const float* __restrict__ b_d,
    const float* __restrict__ fcW, const float* __restrict__ fcb)
{
    extern __shared__ float smem[];
    const int tid = threadIdx.x;
    const int lane = tid & 31;
    const int g = (tid >> 5) & 3;   // gate
    const int kq = tid >> 7;        // k-quarter 0..3
    const int gt = tid & 127;       // tid within quarter-group
    const int cta = blockIdx.x;
    const int grp = cta >> 4;       // barrier group 0..7
    uint32_t sb_base = smem_u32(smem);

    // per-CTA constants: fc weights + x transposed (xT[t*32+b])
    if (tid >= 512 - 16) smem[SFC_F + tid - 496] = fcW[cta * 16 + (tid - 496)];
    for (int idx = tid; idx < 4096; idx += 512) {
        int b = idx & 31, t = idx >> 5;
        smem[XT_F + idx] = x[b * TIN + t];
    }

    #pragma unroll 1
    for (int step = 0; step < NSTEP; step++) {
        const bool dec = (step >= TIN);
        const int p = step & 1;
        const __half* Aperm = dec ? g_Adec : g_Aenc;
        const float* Wih = dec ? Wih_d : Wih_e;
        const float* bias = dec ? b_d : b_e;
        const __half* Hs = g_hstage[p];

        // ---- A-ring prefill (h-independent; overlaps barrier wait) ----
        const __half* Aw = Aperm + (size_t)(cta * 4 + g) * AG_HALF + kq * 8192;
        const float4* Athr = (const float4*)(Aw + lane * 8);
        uint4 Ast[8];
        #pragma unroll
        for (int i = 0; i < 8; i++) Ast[i] = *(const uint4*)(Athr + i * 32);

        // ---- tree-arrive global barrier ----
        __syncthreads();
        if (tid == 0) {
            __threadfence();
            int t = atomicAdd(&g_arr1[grp * 32], 1);
            bool released = false;
            if (t == (step + 1) * 16 - 1) {
                int t2 = atomicAdd(&g_arr2, 1);
                if (t2 == (step + 1) * 8 - 1) {
                    asm volatile("st.release.gpu.global.s32 [%0], %1;"
                                 :: "l"(&g_release), "r"(step + 1) : "memory");
                    released = true;
                }
            }
            if (!released) {
                int v;
                do {
                    asm volatile("ld.acquire.gpu.global.s32 %0, [%1];"
                                 : "=r"(v) : "l"(&g_release) : "memory");
                } while (v < step + 1);
            }
        }
        __syncthreads();

        // ---- single-shot h fetch: quarter-group pulls its full 32 KB ----
        {
            uint32_t db = sb_base + kq * 32768u;
            const char* src = (const char*)Hs + kq * 32768;
            #pragma unroll
            for (int i = 0; i < 16; i++)
                cp_async16(db + (gt + i * 128) * 16, src + (gt + i * 128) * 16);
            asm volatile("cp.async.commit_group;" ::: "memory");
        }

        // ---- decoder input (overlaps cp.async) ----
        const float* sx;
        if (!dec || step == TIN) {
            sx = smem + XT_F + (dec ? (TIN - 1) : step) * 32;
        } else {
            int pg = tid >> 5, b = tid & 31;
            int d0 = step - TIN - 1;
            float v = 0.f;
            #pragma unroll
            for (int j = 0; j < 8; j++)
                v += ldcg_f(&g_ypart[(d0 * NCTA + pg * 8 + j) * 32 + b]);
            smem[SRED_F + pg * 32 + b] = v;
            __syncthreads();
            if (tid < 32) {
                float v2 = fcb[0];
                #pragma unroll
                for (int pgi = 0; pgi < 16; pgi++) v2 += smem[SRED_F + pgi * 32 + tid];
                smem[SX_F + tid] = v2;
            }
            sx = smem + SX_F;
        }

        float d[4][4];
        #pragma unroll
        for (int nb = 0; nb < 4; nb++)
            #pragma unroll
            for (int r = 0; r < 4; r++) d[nb][r] = 0.f;

        // ---- wait once, then straight 32-kb16 MMA run ----
        asm volatile("cp.async.wait_group 0;" ::: "memory");
        asm volatile("bar.sync %0, 128;" :: "r"(1 + kq) : "memory");
        const __half* Bbuf = (const __half*)((const char*)smem + kq * 32768);
        #pragma unroll 8
        for (int l = 0; l < 32; l++) {
            int s = l & 7;
            uint32_t a0[4] = {Ast[s].x, Ast[s].y, Ast[s].z, Ast[s].w};
            #pragma unroll
            for (int nb = 0; nb < 4; nb++) {
                uint2 B0 = *(const uint2*)(Bbuf + l * 512 + nb * 128 + lane * 4);
                uint32_t bf[2] = {B0.x, B0.y};
                mma_f16(d[nb], a0, bf);
            }
            if (l + 8 < 32) Ast[s] = *(const uint4*)(Athr + (l + 8) * 32);
        }

        // ---- epilogue: kq 1..3 write partials; kq 0 accumulates ----
        if (kq > 0) {
            float* exp_ = smem + EXPB_F + (kq - 1) * 2112 + g * 528;
            #pragma unroll
            for (int r = 0; r < 4; r++) {
                int lr = frag_d_row(lane, r);
                #pragma unroll
                for (int nb = 0; nb < 4; nb++) {
                    int n = nb * 8 + frag_d_col(lane, r);
                    exp_[lr * 33 + n] = d[nb][r];
                }
            }
        }
        __syncthreads();
        if (kq == 0) {
            #pragma unroll
            for (int r = 0; r < 4; r++) {
                int lr = frag_d_row(lane, r);
                int grow = g * HID + cta * 16 + lr;
                float wv = Wih[grow];
                float bv = bias[grow];
                #pragma unroll
                for (int nb = 0; nb < 4; nb++) {
                    int n = nb * 8 + frag_d_col(lane, r);
                    float v = d[nb][r] + wv * sx[n] + bv;
                    #pragma unroll
                    for (int q = 1; q < 4; q++)
                        v += smem[EXPB_F + (q - 1) * 2112 + g * 528 + lr * 33 + n];
                    smem[EX_F + g * 528 + lr * 33 + n] = v;
                }
            }
        }
        __syncthreads();

        // ---- fused LSTM cell update: 512 threads x 1 element ----
        {
            int lu = tid >> 5;             // local unit 0..15
            int b = tid & 31;
            int hu = cta * 16 + lu;
            __half* hnext = g_hstage[p ^ 1];
            float gi = smem[EX_F + 0 * 528 + lu * 33 + b];
            float gf = smem[EX_F + 1 * 528 + lu * 33 + b];
            float gg = smem[EX_F + 2 * 528 + lu * 33 + b];
            float go = smem[EX_F + 3 * 528 + lu * 33 + b];
            float si = 1.f / (1.f + expf(-gi));
            float sf = 1.f / (1.f + expf(-gf));
            float so = 1.f / (1.f + expf(-go));
            float cc = sf * g_c[hu * 32 + b] + si * tanhf(gg);
            g_c[hu * 32 + b] = cc;
            float hh = so * tanhf(cc);
            hnext[hidx16(hu, b)] = __float2half_rn(hh);
            if (dec) smem[SHH_F + lu * 33 + b] = hh;
        }
        __syncthreads();

        // ---- decoder fc partial over this CTA's 16 units ----
        if (dec && tid < 32) {
            float y = 0.f;
            #pragma unroll
            for (int lu = 0; lu < 16; lu++)
                y += smem[SHH_F + lu * 33 + tid] * smem[SFC_F + lu];
            g_ypart[((step - TIN) * NCTA + cta) * 32 + tid] = y;
        }
    }
}

// ---------------- host ------------------------------------------------------
extern "C" void kernel_launch(void* const* d_in, const int* in_sizes, int n_in,
                              void* d_out, int out_size) {
    const float *x, *eWih, *eWhh, *eb, *dWih, *dWhh, *db, *fcW, *fcb;
    if (in_sizes[0] == 4096) {
        x    = (const float*)d_in[0];
        eWih = (const float*)d_in[2];
        eWhh = (const float*)d_in[3];
        eb   = (const float*)d_in[4];
        dWih = (const float*)d_in[5];
        dWhh = (const float*)d_in[6];
        db   = (const float*)d_in[7];
        fcW  = (const float*)d_in[8];
        fcb  = (const float*)d_in[9];
    } else {
        dWhh = (const float*)d_in[0];
        dWih = (const float*)d_in[1];
        db   = (const float*)d_in[2];
        eWhh = (const float*)d_in[3];
        eWih = (const float*)d_in[4];
        eb   = (const float*)d_in[5];
        fcW  = (const float*)d_in[6];
        fcb  = (const float*)d_in[7];
        x    = (const float*)d_in[10];
    }
    float* out = (float*)d_out;

    cudaFuncSetAttribute(step_kernel, cudaFuncAttributeMaxDynamicSharedMemorySize, SMEM_BYTES);

    init_kernel<<<256, 256>>>();
    prep_kernel<<<65536, 256>>>(eWhh, 0);
    prep_kernel<<<65536, 256>>>(dWhh, 1);
    step_kernel<<<NCTA, 512, SMEM_BYTES>>>(x, eWih, eb, dWih, db, fcW, fcb);
    final_kernel<<<8, 256>>>(out, fcb);
}